// round 10
// baseline (speedup 1.0000x reference)
#include <cuda_runtime.h>
#include <math.h>
#include <float.h>

// ---------------- static shapes ----------------
#define N0   2048
#define KP0  1843   // int(0.9*2048)
#define KP1  1474   // int(0.8*1843)
#define KP2  1031   // int(0.7*1474)
#define D    256
#define MOUT 4096

// ---------------- device scratch ----------------
__device__ float g_A0[(size_t)N0*N0];
__device__ float g_A1[(size_t)KP0*KP0];
__device__ float g_A2[(size_t)KP1*KP1];
__device__ float g_A3[(size_t)KP2*KP2];
__device__ float g_XW[N0*D];
__device__ float g_Xa[N0*D];
__device__ float g_Xb[N0*D];
__device__ float g_Xup[MOUT*D];
__device__ float g_split[8388608];           // split-K partials (32 MB)
__device__ float g_S[4*N0];                  // s  [H][n]
__device__ float g_T[4*N0];                  // t  [H][n]
__device__ float g_E1[4*N0];                 // exp(s)
__device__ float g_E2[4*N0];                 // exp(0.2 s)
__device__ float g_F1[4*N0];                 // exp(t - m)
__device__ float g_F2[4*N0];                 // exp(0.2t - m)
__device__ float g_Den[4*N0];                // 1/denominator
__device__ float g_Scores[N0];
__device__ float g_Dinv[N0];
__device__ int   g_Idx0[KP0];
__device__ int   g_Idx1[KP1];
__device__ int   g_Idx2[KP2];
__device__ float g_Vals0[KP0];
__device__ float g_Vals1[KP1];
__device__ float g_Vals2[KP2];

// ---------------- fragment loader ----------------
template<int T>
__device__ __forceinline__ void fload(float* d, const float* s)
{
    #pragma unroll
    for (int i = 0; i < T / 4; i++) {
        float4 v = *(const float4*)(s + 4 * i);
        d[4*i+0] = v.x; d[4*i+1] = v.y; d[4*i+2] = v.z; d[4*i+3] = v.w;
    }
    if constexpr (T % 4 == 2) {
        float2 v = *(const float2*)(s + (T/4)*4);
        d[T-2] = v.x; d[T-1] = v.y;
    }
}

// ---------------- templated tiled SGEMM with optional split-K ----------------
// epi 0: none | 1: relu(acc*rs[r]+cb[c]) | 2: acc+rb[r] | 3: relu(acc)
template<int BM, int BN, int BK, int TM, int TN>
__global__ void __launch_bounds__(256) sgemm_t(
    const float* __restrict__ Ag, int lda, long long sAz,
    const float* __restrict__ Bg, int ldb, long long sBz,
    float* __restrict__ Cg, int ldc, long long sCz,
    int M, int N, int K, int transB, int epi, int S, int Kc,
    const float* __restrict__ rsG, long long sRSz,
    const float* __restrict__ cbG, long long sCBz,
    const float* __restrict__ rbG)
{
    __shared__ __align__(16) float As[BK][BM + 4];
    __shared__ __align__(16) float Bs[BK][BN + 4];

    int zb = blockIdx.z, si = 0;
    if (S > 1) { zb = blockIdx.z / S; si = blockIdx.z % S; }
    const int kbeg = si * Kc;
    const int kend = min(K, kbeg + Kc);
    const int Kloc = kend - kbeg;

    const float* A = Ag + (size_t)zb * sAz + kbeg;
    const float* B = Bg + (size_t)zb * sBz + (transB ? (size_t)kbeg : (size_t)kbeg * ldb);
    float*       C = Cg + (size_t)blockIdx.z * sCz;

    const int bm = blockIdx.y * BM, bn = blockIdx.x * BN;
    const int tid = threadIdx.x;
    const int tn = tid % (BN / TN);
    const int tm = tid / (BN / TN);

    float acc[TM][TN];
    #pragma unroll
    for (int i = 0; i < TM; i++)
        #pragma unroll
        for (int j = 0; j < TN; j++) acc[i][j] = 0.f;

    for (int k0 = 0; k0 < Kloc; k0 += BK) {
        #pragma unroll
        for (int l = 0; l < (BM * BK) / 256; l++) {
            int idx = tid + l * 256;
            int r = idx / BK, c = idx % BK;
            int gr = bm + r, gc = k0 + c;
            As[c][r] = (gr < M && gc < Kloc) ? A[(size_t)gr * lda + gc] : 0.f;
        }
        if (!transB) {
            #pragma unroll
            for (int l = 0; l < (BN * BK) / 256; l++) {
                int idx = tid + l * 256;
                int kk = idx / BN, j = idx % BN;
                int gk = k0 + kk, gj = bn + j;
                Bs[kk][j] = (gk < Kloc && gj < N) ? B[(size_t)gk * ldb + gj] : 0.f;
            }
        } else {
            #pragma unroll
            for (int l = 0; l < (BN * BK) / 256; l++) {
                int idx = tid + l * 256;
                int j = idx / BK, kk = idx % BK;
                int gj = bn + j, gk = k0 + kk;
                Bs[kk][j] = (gj < N && gk < Kloc) ? B[(size_t)gj * ldb + gk] : 0.f;
            }
        }
        __syncthreads();

        #pragma unroll
        for (int kk = 0; kk < BK; kk++) {
            float a[TM], b[TN];
            fload<TM>(a, &As[kk][tm * TM]);
            fload<TN>(b, &Bs[kk][tn * TN]);
            #pragma unroll
            for (int i = 0; i < TM; i++)
                #pragma unroll
                for (int j = 0; j < TN; j++)
                    acc[i][j] += a[i] * b[j];
        }
        __syncthreads();
    }

    const float* rs = rsG ? rsG + (size_t)zb * sRSz : nullptr;
    const float* cb = cbG ? cbG + (size_t)zb * sCBz : nullptr;

    #pragma unroll
    for (int i = 0; i < TM; i++) {
        int r = bm + tm * TM + i;
        if (r >= M) continue;
        float rsv = (epi == 1) ? rs[r] : 0.f;
        float rbv = (epi == 2) ? rbG[r] : 0.f;
        #pragma unroll
        for (int j = 0; j < TN; j++) {
            int c = bn + tn * TN + j;
            if (c >= N) continue;
            float v = acc[i][j];
            if (epi == 1)      { v = v * rsv + cb[c]; v = v > 0.f ? v : 0.f; }
            else if (epi == 2) { v = v + rbv; }
            else if (epi == 3) { v = v > 0.f ? v : 0.f; }
            C[(size_t)r * ldc + c] = v;
        }
    }
}

// ---------------- split-K reduce ----------------
__global__ void reduce_split_kernel(
    const float* __restrict__ part, float* __restrict__ C,
    int M, int N, int ldc, long long sCzOut, int S, int epi,
    const float* __restrict__ rsG, long long sRSz,
    const float* __restrict__ cbG, long long sCBz,
    const float* __restrict__ rbG)
{
    int z = blockIdx.y;
    int e = blockIdx.x * 256 + threadIdx.x;
    if (e >= M * N) return;
    size_t mn = (size_t)M * N;
    size_t base = (size_t)z * S * mn + e;
    float v = 0.f;
    for (int s = 0; s < S; s++) v += part[base + (size_t)s * mn];
    int r = e / N, c = e % N;
    if (epi == 1)      { v = v * rsG[(size_t)z * sRSz + r] + cbG[(size_t)z * sCBz + c];
                         v = v > 0.f ? v : 0.f; }
    else if (epi == 2) { v += rbG[r]; }
    else if (epi == 3) { v = v > 0.f ? v : 0.f; }
    C[(size_t)z * sCzOut + (size_t)r * ldc + c] = v;
}

// ---------------- fused GAT aggregation GEMM ----------------
// out[i, c] (c in [0,256)) = sum_k w_{h(c)}[i,k] * XW[k, c], heads fused.
// w recomputed on the fly from adjacency + factored-softmax tables.
// BM=64, BN=256, BK=16, 256 threads (TM=4, TN=16). Split-K into partials.
template<int H>
__global__ void __launch_bounds__(256) agg_gemm(
    const float* __restrict__ A, int n,
    const float* __restrict__ XW,
    const float* __restrict__ sT, const float* __restrict__ F1g,
    const float* __restrict__ F2g,
    const float* __restrict__ sS, const float* __restrict__ E1g,
    const float* __restrict__ E2g,
    float* __restrict__ part, int S, int Kc)
{
    constexpr int C = 256 / H;
    __shared__ __align__(16) float sW[H][16][68];
    __shared__ __align__(16) float sB[16][260];
    __shared__ float rT[4][64], rF1[4][64], rF2[4][64];

    const int si = blockIdx.z;
    const int kbeg = si * Kc;
    const int kend = min(n, kbeg + Kc);
    const int bm = blockIdx.y * 64;
    const int tid = threadIdx.x;
    const int tn = tid & 15, tm = tid >> 4;
    const int hd = (tn * 16) / C;

    // stage per-row constants once
    {
        int h = tid >> 6, r = tid & 63;
        int gr = bm + r;
        float tv = 0.f, f1 = 0.f, f2 = 0.f;
        if (h < H && gr < n) {
            tv = sT[h * n + gr]; f1 = F1g[h * n + gr]; f2 = F2g[h * n + gr];
        }
        rT[h][r] = tv; rF1[h][r] = f1; rF2[h][r] = f2;
    }
    __syncthreads();

    float acc[4][16];
    #pragma unroll
    for (int i = 0; i < 4; i++)
        #pragma unroll
        for (int j = 0; j < 16; j++) acc[i][j] = 0.f;

    for (int k0 = kbeg; k0 < kend; k0 += 16) {
        // A tile -> per-head w tiles
        #pragma unroll
        for (int l = 0; l < 4; l++) {
            int e = tid + l * 256;
            int r = e >> 4, kk = e & 15;
            int gr = bm + r, gk = k0 + kk;
            float a = (gr < n && gk < kend) ? A[(size_t)gr * n + gk] : 0.f;
            bool pos = a > 0.f;
            #pragma unroll
            for (int h = 0; h < H; h++) {
                float w = 0.f;
                if (pos) {
                    float sj = sS[h * n + gk];
                    w = (sj + rT[h][r] > 0.f) ? rF1[h][r] * E1g[h * n + gk]
                                              : rF2[h][r] * E2g[h * n + gk];
                }
                sW[h][kk][r] = w;
            }
        }
        // B tile (XW rows k0..k0+16)
        #pragma unroll
        for (int l = 0; l < 16; l++) {
            int e = tid + l * 256;
            int kk = e >> 8, c = e & 255;
            int gk = k0 + kk;
            sB[kk][c] = (gk < kend) ? XW[(size_t)gk * 256 + c] : 0.f;
        }
        __syncthreads();

        #pragma unroll
        for (int kk = 0; kk < 16; kk++) {
            float b[16], a[4];
            fload<16>(b, &sB[kk][tn * 16]);
            fload<4>(a, &sW[hd][kk][tm * 4]);
            #pragma unroll
            for (int i = 0; i < 4; i++)
                #pragma unroll
                for (int j = 0; j < 16; j++)
                    acc[i][j] += a[i] * b[j];
        }
        __syncthreads();
    }

    // store raw partials
    size_t stride = (size_t)n * 256;
    #pragma unroll
    for (int i = 0; i < 4; i++) {
        int gr = bm + tm * 4 + i;
        if (gr >= n) continue;
        float* dst = part + (size_t)si * stride + (size_t)gr * 256 + tn * 16;
        #pragma unroll
        for (int j = 0; j < 16; j += 4) {
            float4 v = make_float4(acc[i][j], acc[i][j+1], acc[i][j+2], acc[i][j+3]);
            *(float4*)(dst + j) = v;
        }
    }
}

// reduce agg partials: v*deninv[head][r] + b[c], relu
__global__ void agg_reduce_kernel(const float* __restrict__ part, float* __restrict__ Xout,
                                  const float* __restrict__ deninv, const float* __restrict__ b,
                                  int n, int S, int Cshift)
{
    int e = blockIdx.x * 256 + threadIdx.x;
    if (e >= n * 256) return;
    size_t stride = (size_t)n * 256;
    float v = 0.f;
    for (int s = 0; s < S; s++) v += part[(size_t)s * stride + e];
    int r = e >> 8, c = e & 255;
    int h = c >> Cshift;
    v = v * deninv[h * n + r] + b[c];
    Xout[e] = v > 0.f ? v : 0.f;
}

// ---------------- symmetric Gram: out = relu(X X^T), X [4096,256] ----------------
__global__ void __launch_bounds__(256) gram_kernel(const float* __restrict__ X,
                                                   float* __restrict__ out)
{
    __shared__ __align__(16) float sm[64 * 129];
    float (*As)[132] = (float(*)[132])sm;
    float (*Bs)[132] = (float(*)[132])(sm + 16 * 132);
    float (*Ts)[129] = (float(*)[129])sm;

    const int bi = blockIdx.y, bj = blockIdx.x;
    if (bj < bi) return;
    const int bm = bi * 128, bn = bj * 128;
    const int tid = threadIdx.x, tn = tid % 16, tm = tid / 16;

    float acc[8][8];
    #pragma unroll
    for (int i = 0; i < 8; i++)
        #pragma unroll
        for (int j = 0; j < 8; j++) acc[i][j] = 0.f;

    for (int k0 = 0; k0 < 256; k0 += 16) {
        #pragma unroll
        for (int l = 0; l < 8; l++) {
            int idx = tid + l * 256;
            int r = idx / 16, c = idx % 16;
            As[c][r] = X[(size_t)(bm + r) * 256 + k0 + c];
        }
        #pragma unroll
        for (int l = 0; l < 8; l++) {
            int idx = tid + l * 256;
            int r = idx / 16, c = idx % 16;
            Bs[c][r] = X[(size_t)(bn + r) * 256 + k0 + c];
        }
        __syncthreads();
        #pragma unroll
        for (int kk = 0; kk < 16; kk++) {
            float a[8], b[8];
            fload<8>(a, &As[kk][tm * 8]);
            fload<8>(b, &Bs[kk][tn * 8]);
            #pragma unroll
            for (int i = 0; i < 8; i++)
                #pragma unroll
                for (int j = 0; j < 8; j++)
                    acc[i][j] += a[i] * b[j];
        }
        __syncthreads();
    }

    #pragma unroll
    for (int i = 0; i < 8; i++)
        #pragma unroll
        for (int j = 0; j < 8; j++) acc[i][j] = acc[i][j] > 0.f ? acc[i][j] : 0.f;

    #pragma unroll
    for (int i = 0; i < 8; i++) {
        int r = bm + tm * 8 + i;
        #pragma unroll
        for (int j = 0; j < 8; j += 4) {
            float4 v = make_float4(acc[i][j], acc[i][j+1], acc[i][j+2], acc[i][j+3]);
            *(float4*)&out[(size_t)r * MOUT + bn + tn * 8 + j] = v;
        }
    }
    if (bi == bj) return;

    for (int half = 0; half < 2; half++) {
        __syncthreads();
        if ((tm >> 3) == half) {
            int rb = (tm & 7) * 8;
            #pragma unroll
            for (int i = 0; i < 8; i++)
                #pragma unroll
                for (int j = 0; j < 8; j++)
                    Ts[rb + i][tn * 8 + j] = acc[i][j];
        }
        __syncthreads();
        for (int e = tid; e < 128 * 64; e += 256) {
            int c = e >> 6, r = e & 63;
            out[(size_t)(bn + c) * MOUT + bm + half * 64 + r] = Ts[r][c];
        }
    }
}

// ---------------- sym-norm ----------------
__global__ void rowsum_kernel(const float* __restrict__ A, float* __restrict__ dinv, int n)
{
    int i = blockIdx.x, tid = threadIdx.x;
    __shared__ float red[256];
    float sm = 0.f;
    for (int j = tid; j < n; j += 256) sm += A[(size_t)i * n + j];
    red[tid] = sm; __syncthreads();
    for (int off = 128; off > 0; off >>= 1) {
        if (tid < off) red[tid] += red[tid + off];
        __syncthreads();
    }
    if (tid == 0) dinv[i] = 1.f / sqrtf(red[0] + 1.f + 1e-5f);
}

__global__ void norm_kernel(const float* __restrict__ A, const float* __restrict__ dinv,
                            float* __restrict__ An, int n)
{
    int j = blockIdx.x * 256 + threadIdx.x;
    int i = blockIdx.y;
    if (j < n) {
        float v = A[(size_t)i * n + j] + (i == j ? 1.f : 0.f);
        An[(size_t)i * n + j] = dinv[i] * dinv[j] * v;
    }
}

// ---------------- per-head logit projections ----------------
__global__ void st_kernel(const float* __restrict__ XW,
                          const float* __restrict__ a_src, const float* __restrict__ a_dst,
                          float* __restrict__ s, float* __restrict__ t, int H, int C, int n)
{
    int j = blockIdx.x, tid = threadIdx.x;
    __shared__ float sh[512];
    float v = XW[(size_t)j * D + tid];
    sh[tid]       = v * a_src[tid];
    sh[256 + tid] = v * a_dst[tid];
    __syncthreads();
    for (int off = C >> 1; off > 0; off >>= 1) {
        if ((tid & (C - 1)) < off) {
            sh[tid]       += sh[tid + off];
            sh[256 + tid] += sh[256 + tid + off];
        }
        __syncthreads();
    }
    if ((tid & (C - 1)) == 0) {
        int h = tid / C;
        s[h * n + j] = sh[tid];
        t[h * n + j] = sh[256 + tid];
    }
}

__global__ void expst_kernel(const float* __restrict__ s, float* __restrict__ E1,
                             float* __restrict__ E2, int count)
{
    int i = blockIdx.x * 256 + threadIdx.x;
    if (i < count) {
        float v = s[i];
        E1[i] = __expf(v);
        E2[i] = __expf(0.2f * v);
    }
}

// ---------------- denominators + row factors (single masked pass over A) ----------------
__global__ void denom_kernel(const float* __restrict__ A,
                             const float* __restrict__ s, const float* __restrict__ t,
                             const float* __restrict__ E1g, const float* __restrict__ E2g,
                             float* __restrict__ F1, float* __restrict__ F2,
                             float* __restrict__ deninv, int n, int H)
{
    int i = blockIdx.x, tid = threadIdx.x;
    __shared__ float red[256];
    float th[4], mx[4], se1[4], se2[4];
    for (int h = 0; h < H; h++) {
        th[h] = t[h * n + i]; mx[h] = -FLT_MAX; se1[h] = 0.f; se2[h] = 0.f;
    }
    const float* Ar = A + (size_t)i * n;
    for (int j = tid; j < n; j += 256) {
        if (Ar[j] > 0.f) {
            for (int h = 0; h < H; h++) {
                float sj = s[h * n + j];
                mx[h] = fmaxf(mx[h], sj);
                if (sj + th[h] > 0.f) se1[h] += E1g[h * n + j];
                else                  se2[h] += E2g[h * n + j];
            }
        }
    }
    for (int h = 0; h < H; h++) {
        red[tid] = mx[h]; __syncthreads();
        for (int off = 128; off > 0; off >>= 1) {
            if (tid < off) red[tid] = fmaxf(red[tid], red[tid + off]);
            __syncthreads();
        }
        float mxh = red[0]; __syncthreads();
        red[tid] = se1[h]; __syncthreads();
        for (int off = 128; off > 0; off >>= 1) {
            if (tid < off) red[tid] += red[tid + off];
            __syncthreads();
        }
        float s1 = red[0]; __syncthreads();
        red[tid] = se2[h]; __syncthreads();
        for (int off = 128; off > 0; off >>= 1) {
            if (tid < off) red[tid] += red[tid + off];
            __syncthreads();
        }
        if (tid == 0) {
            float s2 = red[0];
            float m = th[h] + mxh;
            m = m > 0.f ? m : 0.2f * m;
            float f1 = __expf(th[h] - m);
            float f2 = __expf(0.2f * th[h] - m);
            F1[h * n + i] = f1;
            F2[h * n + i] = f2;
            deninv[h * n + i] = 1.f / (f1 * s1 + f2 * s2);
        }
        __syncthreads();
    }
}

// ---------------- pooling ----------------
__global__ void scores_kernel(const float* __restrict__ X, const float* __restrict__ Wp,
                              const float* __restrict__ bp, float* __restrict__ scores, int n)
{
    int j = blockIdx.x, tid = threadIdx.x;
    __shared__ float red[256];
    red[tid] = X[(size_t)j * D + tid] * Wp[tid];
    __syncthreads();
    for (int off = 128; off > 0; off >>= 1) {
        if (tid < off) red[tid] += red[tid + off];
        __syncthreads();
    }
    if (tid == 0) scores[j] = 1.f / (1.f + expf(-(red[0] + bp[0])));
}

__global__ void __launch_bounds__(1024) topk_sorted_kernel(
    const float* __restrict__ scores, int n, int k,
    int* __restrict__ idx, float* __restrict__ vals)
{
    __shared__ float sc[2048];
    __shared__ int aux[1024];
    int tid = threadIdx.x;
    for (int i = tid; i < 2048; i += 1024) sc[i] = (i < n) ? scores[i] : -FLT_MAX;
    __syncthreads();
    int flag[2];
    #pragma unroll
    for (int e = 0; e < 2; e++) {
        int i = 2 * tid + e;
        flag[e] = 0;
        if (i < n) {
            float si = sc[i];
            int rank = 0;
            for (int j = 0; j < n; j++) {
                float sj = sc[j];
                rank += (sj > si) || (sj == si && j < i);
            }
            flag[e] = (rank < k) ? 1 : 0;
        }
    }
    int psum = flag[0] + flag[1];
    aux[tid] = psum;
    __syncthreads();
    for (int off = 1; off < 1024; off <<= 1) {
        int v = (tid >= off) ? aux[tid - off] : 0;
        __syncthreads();
        aux[tid] += v;
        __syncthreads();
    }
    int excl = aux[tid] - psum;
    if (flag[0]) { idx[excl] = 2 * tid; vals[excl] = sc[2 * tid]; }
    if (flag[1]) { int p = excl + flag[0]; idx[p] = 2 * tid + 1; vals[p] = sc[2 * tid + 1]; }
}

__global__ void gather_x_kernel(const float* __restrict__ Xin, const int* __restrict__ idx,
                                const float* __restrict__ vals, float* __restrict__ Xout)
{
    int r = blockIdx.x, c = threadIdx.x;
    Xout[(size_t)r * D + c] = Xin[(size_t)idx[r] * D + c] * vals[r];
}

__global__ void gather_a_kernel(const float* __restrict__ Ain, int nin,
                                const int* __restrict__ idx, float* __restrict__ Aout, int k)
{
    int c = blockIdx.x * 256 + threadIdx.x;
    int r = blockIdx.y;
    if (c < k) Aout[(size_t)r * k + c] = Ain[(size_t)idx[r] * nin + idx[c]];
}

__global__ void zero_kernel(float* __restrict__ X, int count)
{
    int i = blockIdx.x * 256 + threadIdx.x;
    if (i < count) X[i] = 0.f;
}

__global__ void scatter_x_kernel(const float* __restrict__ Xin, const int* __restrict__ idx,
                                 float* __restrict__ Xout)
{
    int r = blockIdx.x, c = threadIdx.x;
    Xout[(size_t)idx[r] * D + c] = Xin[(size_t)r * D + c];
}

// ---------------- host orchestration ----------------
struct Bufs {
    float *A0, *A1, *A2, *A3, *XW, *Xa, *Xb, *Xup, *Split;
    float *S, *T, *E1, *E2, *F1, *F2, *Den, *Scores, *Dinv;
    float *Vals0, *Vals1, *Vals2;
    int   *Idx0, *Idx1, *Idx2;
};

static void run_gat(const Bufs& g, const float* Amat, int n,
                    const float* Xin, float* Xout,
                    const float* W, const float* a_s, const float* a_d, const float* b,
                    int H, int C)
{
    // XW = Xin @ W  (M=n, N=256, K=256)
    {
        dim3 grid(4, (n + 31) / 32, 1);
        sgemm_t<32, 64, 16, 2, 4><<<grid, 256>>>(Xin, D, 0, W, D, 0, g.XW, D, 0,
                                                 n, D, D, 0, 0, 1, D,
                                                 nullptr, 0, nullptr, 0, nullptr);
    }
    st_kernel<<<n, 256>>>(g.XW, a_s, a_d, g.S, g.T, H, C, n);
    expst_kernel<<<(H * n + 255) / 256, 256>>>(g.S, g.E1, g.E2, H * n);
    denom_kernel<<<n, 256>>>(Amat, g.S, g.T, g.E1, g.E2, g.F1, g.F2, g.Den, n, H);

    // fused aggregation: all heads, w recomputed on the fly
    int blk = (n + 63) / 64;
    int S = (300 + blk - 1) / blk;
    if (S > 16) S = 16;
    int Smax = 32768 / n;              // partial buffer limit: S*n*256 <= 8388608
    if (S > Smax) S = Smax;
    if (S < 1) S = 1;
    int Kc = (((n + S - 1) / S) + 15) & ~15;
    dim3 grid(1, blk, S);
    if (H == 4) agg_gemm<4><<<grid, 256>>>(Amat, n, g.XW, g.T, g.F1, g.F2,
                                           g.S, g.E1, g.E2, g.Split, S, Kc);
    else        agg_gemm<2><<<grid, 256>>>(Amat, n, g.XW, g.T, g.F1, g.F2,
                                           g.S, g.E1, g.E2, g.Split, S, Kc);
    int Cshift = (C == 64) ? 6 : 7;
    agg_reduce_kernel<<<(n * 256 + 255) / 256, 256>>>(g.Split, Xout, g.Den, b, n, S, Cshift);
}

static void run_pool(const Bufs& g, const float* Xin, float* Xout,
                     const float* Ain, float* Aout, int n, int k,
                     const float* Wp, const float* bp, int* idx, float* vals)
{
    scores_kernel<<<n, 256>>>(Xin, Wp, bp, g.Scores, n);
    topk_sorted_kernel<<<1, 1024>>>(g.Scores, n, k, idx, vals);
    gather_x_kernel<<<k, 256>>>(Xin, idx, vals, Xout);
    dim3 ga((k + 255) / 256, k);
    gather_a_kernel<<<ga, 256>>>(Ain, n, idx, Aout, k);
}

extern "C" void kernel_launch(void* const* d_in, const int* in_sizes, int n_in,
                              void* d_out, int out_size)
{
    const float* A_in    = (const float*)d_in[0];
    const float* X_in    = (const float*)d_in[1];
    const float* W_down  = (const float*)d_in[2];
    const float* as_down = (const float*)d_in[3];
    const float* ad_down = (const float*)d_in[4];
    const float* b_down  = (const float*)d_in[5];
    const float* W_up    = (const float*)d_in[6];
    const float* as_up   = (const float*)d_in[7];
    const float* ad_up   = (const float*)d_in[8];
    const float* b_up    = (const float*)d_in[9];
    const float* W_bot   = (const float*)d_in[10];
    const float* as_bot  = (const float*)d_in[11];
    const float* ad_bot  = (const float*)d_in[12];
    const float* b_bot   = (const float*)d_in[13];
    const float* W_pool  = (const float*)d_in[14];
    const float* b_pool  = (const float*)d_in[15];
    const float* W_ups   = (const float*)d_in[16];
    const float* b_ups   = (const float*)d_in[17];
    float* out = (float*)d_out;

    Bufs g;
    cudaGetSymbolAddress((void**)&g.A0, g_A0);
    cudaGetSymbolAddress((void**)&g.A1, g_A1);
    cudaGetSymbolAddress((void**)&g.A2, g_A2);
    cudaGetSymbolAddress((void**)&g.A3, g_A3);
    cudaGetSymbolAddress((void**)&g.XW, g_XW);
    cudaGetSymbolAddress((void**)&g.Xa, g_Xa);
    cudaGetSymbolAddress((void**)&g.Xb, g_Xb);
    cudaGetSymbolAddress((void**)&g.Xup, g_Xup);
    cudaGetSymbolAddress((void**)&g.Split, g_split);
    cudaGetSymbolAddress((void**)&g.S, g_S);
    cudaGetSymbolAddress((void**)&g.T, g_T);
    cudaGetSymbolAddress((void**)&g.E1, g_E1);
    cudaGetSymbolAddress((void**)&g.E2, g_E2);
    cudaGetSymbolAddress((void**)&g.F1, g_F1);
    cudaGetSymbolAddress((void**)&g.F2, g_F2);
    cudaGetSymbolAddress((void**)&g.Den, g_Den);
    cudaGetSymbolAddress((void**)&g.Scores, g_Scores);
    cudaGetSymbolAddress((void**)&g.Dinv, g_Dinv);
    cudaGetSymbolAddress((void**)&g.Vals0, g_Vals0);
    cudaGetSymbolAddress((void**)&g.Vals1, g_Vals1);
    cudaGetSymbolAddress((void**)&g.Vals2, g_Vals2);
    cudaGetSymbolAddress((void**)&g.Idx0, g_Idx0);
    cudaGetSymbolAddress((void**)&g.Idx1, g_Idx1);
    cudaGetSymbolAddress((void**)&g.Idx2, g_Idx2);

    // --- sym-norm ---
    rowsum_kernel<<<N0, 256>>>(A_in, g.Dinv, N0);
    dim3 gn((N0 + 255) / 256, N0);
    norm_kernel<<<gn, 256>>>(A_in, g.Dinv, g.A0, N0);

    // --- encoder ---
    run_gat(g, g.A0, N0, X_in, g.Xa,
            W_down + 0 * D * D, as_down + 0 * D, ad_down + 0 * D, b_down + 0 * D, 4, 64);
    run_pool(g, g.Xa, g.Xb, g.A0, g.A1, N0, KP0, W_pool + 0 * D, b_pool + 0, g.Idx0, g.Vals0);

    run_gat(g, g.A1, KP0, g.Xb, g.Xb,
            W_down + 1 * D * D, as_down + 1 * D, ad_down + 1 * D, b_down + 1 * D, 4, 64);
    run_pool(g, g.Xb, g.Xa, g.A1, g.A2, KP0, KP1, W_pool + 1 * D, b_pool + 1, g.Idx1, g.Vals1);

    run_gat(g, g.A2, KP1, g.Xa, g.Xa,
            W_down + 2 * D * D, as_down + 2 * D, ad_down + 2 * D, b_down + 2 * D, 4, 64);
    run_pool(g, g.Xa, g.Xb, g.A2, g.A3, KP1, KP2, W_pool + 2 * D, b_pool + 2, g.Idx2, g.Vals2);

    // --- bottom (H=2, C=128) ---
    run_gat(g, g.A3, KP2, g.Xb, g.Xb, W_bot, as_bot, ad_bot, b_bot, 2, 128);

    // --- decoder ---
    zero_kernel<<<(KP1 * D + 255) / 256, 256>>>(g.Xa, KP1 * D);
    scatter_x_kernel<<<KP2, 256>>>(g.Xb, g.Idx2, g.Xa);
    run_gat(g, g.A2, KP1, g.Xa, g.Xa,
            W_up + 0 * D * D, as_up + 0 * D, ad_up + 0 * D, b_up + 0 * D, 4, 64);

    zero_kernel<<<(KP0 * D + 255) / 256, 256>>>(g.Xb, KP0 * D);
    scatter_x_kernel<<<KP1, 256>>>(g.Xa, g.Idx1, g.Xb);
    run_gat(g, g.A1, KP0, g.Xb, g.Xb,
            W_up + 1 * D * D, as_up + 1 * D, ad_up + 1 * D, b_up + 1 * D, 4, 64);

    zero_kernel<<<(N0 * D + 255) / 256, 256>>>(g.Xa, N0 * D);
    scatter_x_kernel<<<KP0, 256>>>(g.Xb, g.Idx0, g.Xa);
    run_gat(g, g.A0, N0, g.Xa, g.Xa,
            W_up + 2 * D * D, as_up + 2 * D, ad_up + 2 * D, b_up + 2 * D, 4, 64);

    // --- upsampler: X_up = W_ups @ X + b_ups[:,None]  (M=4096, N=256, K=2048) ---
    {
        const int S = 4, Kc = (N0 + S - 1) / S;
        dim3 grid(4, 64, S);
        sgemm_t<64, 64, 16, 4, 4><<<grid, 256>>>(W_ups, N0, 0, g.Xa, D, 0,
                                                 g.Split, D, (long long)MOUT * D,
                                                 MOUT, D, N0, 0, 0, S, Kc,
                                                 nullptr, 0, nullptr, 0, nullptr);
        dim3 rg((MOUT * D + 255) / 256, 1);
        reduce_split_kernel<<<rg, 256>>>(g.Split, g.Xup, MOUT, D, D, 0, S, 2,
                                         nullptr, 0, nullptr, 0, b_ups);
    }

    // --- A_up = relu(X_up @ X_up^T), symmetric (M=N=4096, K=256) ---
    {
        dim3 grid(32, 32);
        gram_kernel<<<grid, 256>>>(g.Xup, out);
    }
}

// round 17
// speedup vs baseline: 1.5403x; 1.5403x over previous
#include <cuda_runtime.h>
#include <math.h>
#include <float.h>

// ---------------- static shapes ----------------
#define N0   2048
#define KP0  1843   // int(0.9*2048)
#define KP1  1474   // int(0.8*1843)
#define KP2  1031   // int(0.7*1474)
#define D    256
#define MOUT 4096

// ---------------- device scratch ----------------
__device__ float g_A0[(size_t)N0*N0];
__device__ float g_A1[(size_t)KP0*KP0];
__device__ float g_A2[(size_t)KP1*KP1];
__device__ float g_A3[(size_t)KP2*KP2];
__device__ float g_P [(size_t)4*N0*N0];      // attention weights, per head
__device__ float g_XW[N0*D];
__device__ float g_Xa[N0*D];
__device__ float g_Xb[N0*D];
__device__ float g_Xup[MOUT*D];
__device__ float g_split[8388608];           // split-K partials (32 MB)
__device__ float g_S[4*N0];                  // [H][n]
__device__ float g_T[4*N0];                  // [H][n]
__device__ float g_Den[4*N0];                // 1/denominator, [H][n]
__device__ float g_Scores[N0];
__device__ float g_Dinv[N0];
__device__ int   g_Idx0[KP0];
__device__ int   g_Idx1[KP1];
__device__ int   g_Idx2[KP2];
__device__ float g_Vals0[KP0];
__device__ float g_Vals1[KP1];
__device__ float g_Vals2[KP2];

// ---------------- fragment loader ----------------
template<int T>
__device__ __forceinline__ void fload(float* d, const float* s)
{
    if constexpr (T % 4 == 0) {
        #pragma unroll
        for (int i = 0; i < T / 4; i++) {
            float4 v = *(const float4*)(s + 4 * i);
            d[4*i+0] = v.x; d[4*i+1] = v.y; d[4*i+2] = v.z; d[4*i+3] = v.w;
        }
    } else if constexpr (T % 2 == 0) {
        #pragma unroll
        for (int i = 0; i < T / 2; i++) {
            float2 v = *(const float2*)(s + 2 * i);
            d[2*i+0] = v.x; d[2*i+1] = v.y;
        }
    } else {
        #pragma unroll
        for (int i = 0; i < T; i++) d[i] = s[i];
    }
}

// ---------------- templated tiled SGEMM with optional split-K ----------------
// blockIdx.z = zb*S + si. K chunk [si*Kc, min(K,(si+1)*Kc)).
// epi 0: none | 1: relu(acc*rs[r]+cb[c]) | 2: acc+rb[r] | 3: relu(acc)
template<int BM, int BN, int BK, int TM, int TN>
__global__ void __launch_bounds__(256) sgemm_t(
    const float* __restrict__ Ag, int lda, long long sAz,
    const float* __restrict__ Bg, int ldb, long long sBz,
    float* __restrict__ Cg, int ldc, long long sCz,
    int M, int N, int K, int transB, int epi, int S, int Kc,
    const float* __restrict__ rsG, long long sRSz,
    const float* __restrict__ cbG, long long sCBz,
    const float* __restrict__ rbG)
{
    __shared__ __align__(16) float As[BK][BM + 4];
    __shared__ __align__(16) float Bs[BK][BN + 4];

    int zb = blockIdx.z, si = 0;
    if (S > 1) { zb = blockIdx.z / S; si = blockIdx.z % S; }
    const int kbeg = si * Kc;
    const int kend = min(K, kbeg + Kc);
    const int Kloc = kend - kbeg;

    const float* A = Ag + (size_t)zb * sAz + kbeg;
    const float* B = Bg + (size_t)zb * sBz + (transB ? (size_t)kbeg : (size_t)kbeg * ldb);
    float*       C = Cg + (size_t)blockIdx.z * sCz;

    const int bm = blockIdx.y * BM, bn = blockIdx.x * BN;
    const int tid = threadIdx.x;
    const int tn = tid % (BN / TN);
    const int tm = tid / (BN / TN);

    float acc[TM][TN];
    #pragma unroll
    for (int i = 0; i < TM; i++)
        #pragma unroll
        for (int j = 0; j < TN; j++) acc[i][j] = 0.f;

    for (int k0 = 0; k0 < Kloc; k0 += BK) {
        #pragma unroll
        for (int l = 0; l < (BM * BK) / 256; l++) {
            int idx = tid + l * 256;
            int r = idx / BK, c = idx % BK;
            int gr = bm + r, gc = k0 + c;
            As[c][r] = (gr < M && gc < Kloc) ? A[(size_t)gr * lda + gc] : 0.f;
        }
        if (!transB) {
            #pragma unroll
            for (int l = 0; l < (BN * BK) / 256; l++) {
                int idx = tid + l * 256;
                int kk = idx / BN, j = idx % BN;
                int gk = k0 + kk, gj = bn + j;
                Bs[kk][j] = (gk < Kloc && gj < N) ? B[(size_t)gk * ldb + gj] : 0.f;
            }
        } else {
            #pragma unroll
            for (int l = 0; l < (BN * BK) / 256; l++) {
                int idx = tid + l * 256;
                int j = idx / BK, kk = idx % BK;
                int gj = bn + j, gk = k0 + kk;
                Bs[kk][j] = (gj < N && gk < Kloc) ? B[(size_t)gj * ldb + gk] : 0.f;
            }
        }
        __syncthreads();

        #pragma unroll
        for (int kk = 0; kk < BK; kk++) {
            float a[TM], b[TN];
            fload<TM>(a, &As[kk][tm * TM]);
            fload<TN>(b, &Bs[kk][tn * TN]);
            #pragma unroll
            for (int i = 0; i < TM; i++)
                #pragma unroll
                for (int j = 0; j < TN; j++)
                    acc[i][j] += a[i] * b[j];
        }
        __syncthreads();
    }

    const float* rs = rsG ? rsG + (size_t)zb * sRSz : nullptr;
    const float* cb = cbG ? cbG + (size_t)zb * sCBz : nullptr;

    #pragma unroll
    for (int i = 0; i < TM; i++) {
        int r = bm + tm * TM + i;
        if (r >= M) continue;
        float rsv = (epi == 1) ? rs[r] : 0.f;
        float rbv = (epi == 2) ? rbG[r] : 0.f;
        #pragma unroll
        for (int j = 0; j < TN; j++) {
            int c = bn + tn * TN + j;
            if (c >= N) continue;
            float v = acc[i][j];
            if (epi == 1)      { v = v * rsv + cb[c]; v = v > 0.f ? v : 0.f; }
            else if (epi == 2) { v = v + rbv; }
            else if (epi == 3) { v = v > 0.f ? v : 0.f; }
            C[(size_t)r * ldc + c] = v;
        }
    }
}

// ---------------- split-K reduce (fixed order -> deterministic) ----------------
__global__ void reduce_split_kernel(
    const float* __restrict__ part, float* __restrict__ C,
    int M, int N, int ldc, long long sCzOut, int S, int epi,
    const float* __restrict__ rsG, long long sRSz,
    const float* __restrict__ cbG, long long sCBz,
    const float* __restrict__ rbG)
{
    int z = blockIdx.y;
    int e = blockIdx.x * 256 + threadIdx.x;
    if (e >= M * N) return;
    size_t mn = (size_t)M * N;
    size_t base = (size_t)z * S * mn + e;
    float v = 0.f;
    for (int s = 0; s < S; s++) v += part[base + (size_t)s * mn];
    int r = e / N, c = e % N;
    if (epi == 1)      { v = v * rsG[(size_t)z * sRSz + r] + cbG[(size_t)z * sCBz + c];
                         v = v > 0.f ? v : 0.f; }
    else if (epi == 2) { v += rbG[r]; }
    else if (epi == 3) { v = v > 0.f ? v : 0.f; }
    C[(size_t)z * sCzOut + (size_t)r * ldc + c] = v;
}

// ---------------- symmetric Gram: out = relu(X X^T), X [4096,256] ----------------
__global__ void __launch_bounds__(256) gram_kernel(const float* __restrict__ X,
                                                   float* __restrict__ out)
{
    __shared__ __align__(16) float sm[64 * 129];
    float (*As)[132] = (float(*)[132])sm;
    float (*Bs)[132] = (float(*)[132])(sm + 16 * 132);
    float (*Ts)[129] = (float(*)[129])sm;

    const int bi = blockIdx.y, bj = blockIdx.x;
    if (bj < bi) return;
    const int bm = bi * 128, bn = bj * 128;
    const int tid = threadIdx.x, tn = tid % 16, tm = tid / 16;

    float acc[8][8];
    #pragma unroll
    for (int i = 0; i < 8; i++)
        #pragma unroll
        for (int j = 0; j < 8; j++) acc[i][j] = 0.f;

    for (int k0 = 0; k0 < 256; k0 += 16) {
        #pragma unroll
        for (int l = 0; l < 8; l++) {
            int idx = tid + l * 256;
            int r = idx / 16, c = idx % 16;
            As[c][r] = X[(size_t)(bm + r) * 256 + k0 + c];
        }
        #pragma unroll
        for (int l = 0; l < 8; l++) {
            int idx = tid + l * 256;
            int r = idx / 16, c = idx % 16;
            Bs[c][r] = X[(size_t)(bn + r) * 256 + k0 + c];
        }
        __syncthreads();
        #pragma unroll
        for (int kk = 0; kk < 16; kk++) {
            float a[8], b[8];
            fload<8>(a, &As[kk][tm * 8]);
            fload<8>(b, &Bs[kk][tn * 8]);
            #pragma unroll
            for (int i = 0; i < 8; i++)
                #pragma unroll
                for (int j = 0; j < 8; j++)
                    acc[i][j] += a[i] * b[j];
        }
        __syncthreads();
    }

    #pragma unroll
    for (int i = 0; i < 8; i++)
        #pragma unroll
        for (int j = 0; j < 8; j++) acc[i][j] = acc[i][j] > 0.f ? acc[i][j] : 0.f;

    #pragma unroll
    for (int i = 0; i < 8; i++) {
        int r = bm + tm * 8 + i;
        #pragma unroll
        for (int j = 0; j < 8; j += 4) {
            float4 v = make_float4(acc[i][j], acc[i][j+1], acc[i][j+2], acc[i][j+3]);
            *(float4*)&out[(size_t)r * MOUT + bn + tn * 8 + j] = v;
        }
    }
    if (bi == bj) return;

    for (int half = 0; half < 2; half++) {
        __syncthreads();
        if ((tm >> 3) == half) {
            int rb = (tm & 7) * 8;
            #pragma unroll
            for (int i = 0; i < 8; i++)
                #pragma unroll
                for (int j = 0; j < 8; j++)
                    Ts[rb + i][tn * 8 + j] = acc[i][j];
        }
        __syncthreads();
        for (int e = tid; e < 128 * 64; e += 256) {
            int c = e >> 6, r = e & 63;
            out[(size_t)(bn + c) * MOUT + bm + half * 64 + r] = Ts[r][c];
        }
    }
}

// ---------------- sym-norm ----------------
__global__ void rowsum_kernel(const float* __restrict__ A, float* __restrict__ dinv, int n)
{
    int i = blockIdx.x, tid = threadIdx.x;
    __shared__ float red[256];
    float sm = 0.f;
    for (int j = tid; j < n; j += 256) sm += A[(size_t)i * n + j];
    red[tid] = sm; __syncthreads();
    for (int off = 128; off > 0; off >>= 1) {
        if (tid < off) red[tid] += red[tid + off];
        __syncthreads();
    }
    if (tid == 0) dinv[i] = 1.f / sqrtf(red[0] + 1.f + 1e-5f);
}

__global__ void norm_kernel(const float* __restrict__ A, const float* __restrict__ dinv,
                            float* __restrict__ An, int n)
{
    int j = blockIdx.x * 256 + threadIdx.x;
    int i = blockIdx.y;
    if (j < n) {
        float v = A[(size_t)i * n + j] + (i == j ? 1.f : 0.f);
        An[(size_t)i * n + j] = dinv[i] * dinv[j] * v;
    }
}

// ---------------- per-head logit projections ----------------
__global__ void st_kernel(const float* __restrict__ XW,
                          const float* __restrict__ a_src, const float* __restrict__ a_dst,
                          float* __restrict__ s, float* __restrict__ t, int H, int C, int n)
{
    int j = blockIdx.x, tid = threadIdx.x;
    __shared__ float sh[512];
    float v = XW[(size_t)j * D + tid];
    sh[tid]       = v * a_src[tid];
    sh[256 + tid] = v * a_dst[tid];
    __syncthreads();
    for (int off = C >> 1; off > 0; off >>= 1) {
        if ((tid & (C - 1)) < off) {
            sh[tid]       += sh[tid + off];
            sh[256 + tid] += sh[256 + tid + off];
        }
        __syncthreads();
    }
    if ((tid & (C - 1)) == 0) {
        int h = tid / C;
        s[h * n + j] = sh[tid];
        t[h * n + j] = sh[256 + tid];
    }
}

// ---------------- masked softmax weights ----------------
// pass1: per-row masked max of s_j (exact shift: max_j lrelu(t+s_j) = lrelu(t + max_j s_j))
// pass2: w = exp(lrelu(t_i+s_j) - mh)
__global__ void attn_softmax_kernel(const float* __restrict__ A,
                                    const float* __restrict__ s, const float* __restrict__ t,
                                    float* __restrict__ P, float* __restrict__ deninv,
                                    int n, int H)
{
    int i = blockIdx.x, tid = threadIdx.x;
    __shared__ float red[256];
    __shared__ float mhs[4];
    float th[4], mx[4], sum[4];
    for (int h = 0; h < H; h++) { th[h] = t[h * n + i]; mx[h] = -FLT_MAX; sum[h] = 0.f; }

    const float* Ar = A + (size_t)i * n;
    for (int j = tid; j < n; j += 256) {
        if (Ar[j] > 0.f)
            for (int h = 0; h < H; h++) mx[h] = fmaxf(mx[h], s[h * n + j]);
    }
    for (int h = 0; h < H; h++) {
        red[tid] = mx[h]; __syncthreads();
        for (int off = 128; off > 0; off >>= 1) {
            if (tid < off) red[tid] = fmaxf(red[tid], red[tid + off]);
            __syncthreads();
        }
        if (tid == 0) {
            float m = th[h] + red[0];
            mhs[h] = m > 0.f ? m : 0.2f * m;
        }
        __syncthreads();
    }
    float mh[4];
    for (int h = 0; h < H; h++) mh[h] = mhs[h];

    size_t np2 = (size_t)n * n;
    for (int j = tid; j < n; j += 256) {
        float a = Ar[j];
        for (int h = 0; h < H; h++) {
            float w = 0.f;
            if (a > 0.f) {
                float l = th[h] + s[h * n + j];
                l = l > 0.f ? l : 0.2f * l;
                w = __expf(l - mh[h]);
                sum[h] += w;
            }
            P[h * np2 + (size_t)i * n + j] = w;
        }
    }
    for (int h = 0; h < H; h++) {
        red[tid] = sum[h]; __syncthreads();
        for (int off = 128; off > 0; off >>= 1) {
            if (tid < off) red[tid] += red[tid + off];
            __syncthreads();
        }
        if (tid == 0) deninv[h * n + i] = 1.f / red[0];
        __syncthreads();
    }
}

// ---------------- pooling ----------------
__global__ void scores_kernel(const float* __restrict__ X, const float* __restrict__ Wp,
                              const float* __restrict__ bp, float* __restrict__ scores, int n)
{
    int j = blockIdx.x, tid = threadIdx.x;
    __shared__ float red[256];
    red[tid] = X[(size_t)j * D + tid] * Wp[tid];
    __syncthreads();
    for (int off = 128; off > 0; off >>= 1) {
        if (tid < off) red[tid] += red[tid + off];
        __syncthreads();
    }
    if (tid == 0) scores[j] = 1.f / (1.f + expf(-(red[0] + bp[0])));
}

// top-k as keep-flag + prefix-sum compaction -> SORTED indices (same selected set)
__global__ void __launch_bounds__(1024) topk_sorted_kernel(
    const float* __restrict__ scores, int n, int k,
    int* __restrict__ idx, float* __restrict__ vals)
{
    __shared__ float sc[2048];
    __shared__ int aux[1024];
    int tid = threadIdx.x;
    for (int i = tid; i < 2048; i += 1024) sc[i] = (i < n) ? scores[i] : -FLT_MAX;
    __syncthreads();
    int flag[2];
    #pragma unroll
    for (int e = 0; e < 2; e++) {
        int i = 2 * tid + e;
        flag[e] = 0;
        if (i < n) {
            float si = sc[i];
            int rank = 0;
            for (int j = 0; j < n; j++) {
                float sj = sc[j];
                rank += (sj > si) || (sj == si && j < i);
            }
            flag[e] = (rank < k) ? 1 : 0;
        }
    }
    int psum = flag[0] + flag[1];
    aux[tid] = psum;
    __syncthreads();
    for (int off = 1; off < 1024; off <<= 1) {
        int v = (tid >= off) ? aux[tid - off] : 0;
        __syncthreads();
        aux[tid] += v;
        __syncthreads();
    }
    int excl = aux[tid] - psum;
    if (flag[0]) { idx[excl] = 2 * tid; vals[excl] = sc[2 * tid]; }
    if (flag[1]) { int p = excl + flag[0]; idx[p] = 2 * tid + 1; vals[p] = sc[2 * tid + 1]; }
}

__global__ void gather_x_kernel(const float* __restrict__ Xin, const int* __restrict__ idx,
                                const float* __restrict__ vals, float* __restrict__ Xout)
{
    int r = blockIdx.x, c = threadIdx.x;
    Xout[(size_t)r * D + c] = Xin[(size_t)idx[r] * D + c] * vals[r];
}

__global__ void gather_a_kernel(const float* __restrict__ Ain, int nin,
                                const int* __restrict__ idx, float* __restrict__ Aout, int k)
{
    int c = blockIdx.x * 256 + threadIdx.x;
    int r = blockIdx.y;
    if (c < k) Aout[(size_t)r * k + c] = Ain[(size_t)idx[r] * nin + idx[c]];
}

__global__ void zero_kernel(float* __restrict__ X, int count)
{
    int i = blockIdx.x * 256 + threadIdx.x;
    if (i < count) X[i] = 0.f;
}

__global__ void scatter_x_kernel(const float* __restrict__ Xin, const int* __restrict__ idx,
                                 float* __restrict__ Xout)
{
    int r = blockIdx.x, c = threadIdx.x;
    Xout[(size_t)idx[r] * D + c] = Xin[(size_t)r * D + c];
}

// ---------------- host orchestration ----------------
struct Bufs {
    float *A0, *A1, *A2, *A3, *P, *XW, *Xa, *Xb, *Xup, *Split;
    float *S, *T, *Den, *Scores, *Dinv;
    float *Vals0, *Vals1, *Vals2;
    int   *Idx0, *Idx1, *Idx2;
};

static void run_gat(const Bufs& g, const float* Amat, int n,
                    const float* Xin, float* Xout,
                    const float* W, const float* a_s, const float* a_d, const float* b,
                    int H, int C)
{
    // XW = Xin @ W  (M=n, N=256, K=256)
    {
        dim3 grid(4, (n + 31) / 32, 1);
        sgemm_t<32, 64, 16, 2, 4><<<grid, 256>>>(Xin, D, 0, W, D, 0, g.XW, D, 0,
                                                 n, D, D, 0, 0, 1, D,
                                                 nullptr, 0, nullptr, 0, nullptr);
    }
    st_kernel<<<n, 256>>>(g.XW, a_s, a_d, g.S, g.T, H, C, n);
    attn_softmax_kernel<<<n, 256>>>(Amat, g.S, g.T, g.P, g.Den, n, H);

    // out_h = relu((P_h @ XW_h) * deninv + b_h): 128x64 tiles + split-K S=8
    // NOTE: grid.x must cover C (bottom layer has C=128 -> 2 column tiles)
    const int S = 8;
    int Kc = (((n + S - 1) / S) + 15) & ~15;
    {
        dim3 grid((C + 63) / 64, (n + 127) / 128, H * S);
        sgemm_t<128, 64, 16, 8, 4><<<grid, 256>>>(g.P, n, (long long)n * n,
                                                  g.XW, D, C,
                                                  g.Split, C, (long long)n * C,
                                                  n, C, n, 0, 0, S, Kc,
                                                  nullptr, 0, nullptr, 0, nullptr);
    }
    dim3 rg((n * C + 255) / 256, H);
    reduce_split_kernel<<<rg, 256>>>(g.Split, Xout, n, C, D, C, S, 1,
                                     g.Den, n, b, C, nullptr);
}

static void run_pool(const Bufs& g, const float* Xin, float* Xout,
                     const float* Ain, float* Aout, int n, int k,
                     const float* Wp, const float* bp, int* idx, float* vals)
{
    scores_kernel<<<n, 256>>>(Xin, Wp, bp, g.Scores, n);
    topk_sorted_kernel<<<1, 1024>>>(g.Scores, n, k, idx, vals);
    gather_x_kernel<<<k, 256>>>(Xin, idx, vals, Xout);
    dim3 ga((k + 255) / 256, k);
    gather_a_kernel<<<ga, 256>>>(Ain, n, idx, Aout, k);
}

extern "C" void kernel_launch(void* const* d_in, const int* in_sizes, int n_in,
                              void* d_out, int out_size)
{
    const float* A_in    = (const float*)d_in[0];
    const float* X_in    = (const float*)d_in[1];
    const float* W_down  = (const float*)d_in[2];
    const float* as_down = (const float*)d_in[3];
    const float* ad_down = (const float*)d_in[4];
    const float* b_down  = (const float*)d_in[5];
    const float* W_up    = (const float*)d_in[6];
    const float* as_up   = (const float*)d_in[7];
    const float* ad_up   = (const float*)d_in[8];
    const float* b_up    = (const float*)d_in[9];
    const float* W_bot   = (const float*)d_in[10];
    const float* as_bot  = (const float*)d_in[11];
    const float* ad_bot  = (const float*)d_in[12];
    const float* b_bot   = (const float*)d_in[13];
    const float* W_pool  = (const float*)d_in[14];
    const float* b_pool  = (const float*)d_in[15];
    const float* W_ups   = (const float*)d_in[16];
    const float* b_ups   = (const float*)d_in[17];
    float* out = (float*)d_out;

    Bufs g;
    cudaGetSymbolAddress((void**)&g.A0, g_A0);
    cudaGetSymbolAddress((void**)&g.A1, g_A1);
    cudaGetSymbolAddress((void**)&g.A2, g_A2);
    cudaGetSymbolAddress((void**)&g.A3, g_A3);
    cudaGetSymbolAddress((void**)&g.P,  g_P);
    cudaGetSymbolAddress((void**)&g.XW, g_XW);
    cudaGetSymbolAddress((void**)&g.Xa, g_Xa);
    cudaGetSymbolAddress((void**)&g.Xb, g_Xb);
    cudaGetSymbolAddress((void**)&g.Xup, g_Xup);
    cudaGetSymbolAddress((void**)&g.Split, g_split);
    cudaGetSymbolAddress((void**)&g.S, g_S);
    cudaGetSymbolAddress((void**)&g.T, g_T);
    cudaGetSymbolAddress((void**)&g.Den, g_Den);
    cudaGetSymbolAddress((void**)&g.Scores, g_Scores);
    cudaGetSymbolAddress((void**)&g.Dinv, g_Dinv);
    cudaGetSymbolAddress((void**)&g.Vals0, g_Vals0);
    cudaGetSymbolAddress((void**)&g.Vals1, g_Vals1);
    cudaGetSymbolAddress((void**)&g.Vals2, g_Vals2);
    cudaGetSymbolAddress((void**)&g.Idx0, g_Idx0);
    cudaGetSymbolAddress((void**)&g.Idx1, g_Idx1);
    cudaGetSymbolAddress((void**)&g.Idx2, g_Idx2);

    // --- sym-norm ---
    rowsum_kernel<<<N0, 256>>>(A_in, g.Dinv, N0);
    dim3 gn((N0 + 255) / 256, N0);
    norm_kernel<<<gn, 256>>>(A_in, g.Dinv, g.A0, N0);

    // --- encoder ---
    run_gat(g, g.A0, N0, X_in, g.Xa,
            W_down + 0 * D * D, as_down + 0 * D, ad_down + 0 * D, b_down + 0 * D, 4, 64);
    run_pool(g, g.Xa, g.Xb, g.A0, g.A1, N0, KP0, W_pool + 0 * D, b_pool + 0, g.Idx0, g.Vals0);

    run_gat(g, g.A1, KP0, g.Xb, g.Xb,
            W_down + 1 * D * D, as_down + 1 * D, ad_down + 1 * D, b_down + 1 * D, 4, 64);
    run_pool(g, g.Xb, g.Xa, g.A1, g.A2, KP0, KP1, W_pool + 1 * D, b_pool + 1, g.Idx1, g.Vals1);

    run_gat(g, g.A2, KP1, g.Xa, g.Xa,
            W_down + 2 * D * D, as_down + 2 * D, ad_down + 2 * D, b_down + 2 * D, 4, 64);
    run_pool(g, g.Xa, g.Xb, g.A2, g.A3, KP1, KP2, W_pool + 2 * D, b_pool + 2, g.Idx2, g.Vals2);

    // --- bottom (H=2, C=128) ---
    run_gat(g, g.A3, KP2, g.Xb, g.Xb, W_bot, as_bot, ad_bot, b_bot, 2, 128);

    // --- decoder ---
    zero_kernel<<<(KP1 * D + 255) / 256, 256>>>(g.Xa, KP1 * D);
    scatter_x_kernel<<<KP2, 256>>>(g.Xb, g.Idx2, g.Xa);
    run_gat(g, g.A2, KP1, g.Xa, g.Xa,
            W_up + 0 * D * D, as_up + 0 * D, ad_up + 0 * D, b_up + 0 * D, 4, 64);

    zero_kernel<<<(KP0 * D + 255) / 256, 256>>>(g.Xb, KP0 * D);
    scatter_x_kernel<<<KP1, 256>>>(g.Xa, g.Idx1, g.Xb);
    run_gat(g, g.A1, KP0, g.Xb, g.Xb,
            W_up + 1 * D * D, as_up + 1 * D, ad_up + 1 * D, b_up + 1 * D, 4, 64);

    zero_kernel<<<(N0 * D + 255) / 256, 256>>>(g.Xa, N0 * D);
    scatter_x_kernel<<<KP0, 256>>>(g.Xb, g.Idx0, g.Xa);
    run_gat(g, g.A0, N0, g.Xa, g.Xa,
            W_up + 2 * D * D, as_up + 2 * D, ad_up + 2 * D, b_up + 2 * D, 4, 64);

    // --- upsampler: X_up = W_ups @ X + b_ups[:,None]  (M=4096, N=256, K=2048) ---
    {
        const int S = 8;
        int Kc = (((N0 + S - 1) / S) + 15) & ~15;
        dim3 grid(4, 32, S);
        sgemm_t<128, 64, 16, 8, 4><<<grid, 256>>>(W_ups, N0, 0, g.Xa, D, 0,
                                                  g.Split, D, (long long)MOUT * D,
                                                  MOUT, D, N0, 0, 0, S, Kc,
                                                  nullptr, 0, nullptr, 0, nullptr);
        dim3 rg((MOUT * D + 255) / 256, 1);
        reduce_split_kernel<<<rg, 256>>>(g.Split, g.Xup, MOUT, D, D, 0, S, 2,
                                         nullptr, 0, nullptr, 0, b_ups);
    }

    // --- A_up = relu(X_up @ X_up^T), symmetric (M=N=4096, K=256) ---
    {
        dim3 grid(32, 32);
        gram_kernel<<<grid, 256>>>(g.Xup, out);
    }
}